// round 2
// baseline (speedup 1.0000x reference)
#include <cuda_runtime.h>

// Problem constants (W=400, H=352, D=5)
#define BB 2
#define CC 64
#define NN (64 * 2048)      // RH*RW = 131072 points per batch
#define WW 400
#define HH 352
#define DD 5
#define DWH (DD * WW * HH)  // 704000 cells per batch
#define TILE 1000           // cells per block (704000 / 1000 = 704); 1000*4B is 16B-aligned

// Scratch: winner point-index per (batch, cell). -1 = empty.
__device__ int g_winner[BB * DWH];

__global__ void init_winner_kernel() {
    int i = blockIdx.x * blockDim.x + threadIdx.x;
    int4* p = reinterpret_cast<int4*>(g_winner);
    if (i < (BB * DWH) / 4) {
        p[i] = make_int4(-1, -1, -1, -1);
    }
}

__global__ void scatter_winner_kernel(const float* __restrict__ xyz) {
    int t = blockIdx.x * blockDim.x + threadIdx.x;
    if (t >= BB * NN) return;
    int b = t >> 17;          // NN = 2^17
    int n = t & (NN - 1);

    const float xp = xyz[(b * 3 + 0) * NN + n];
    const float yp = xyz[(b * 3 + 1) * NN + n];
    const float zp = xyz[(b * 3 + 2) * NN + n];

    if (!(zp >= -3.0f && zp < 1.0f)) return;
    int zbin = (int)floorf(__fdiv_rn(zp + 3.0f, 0.8f));
    if (zbin < 0 || zbin >= DD) return;

    // x_img = trunc(-yp/0.2) + 200, clip [0, W-1]
    int xi = (int)__fdiv_rn(-yp, 0.2f) + 200;
    xi = min(max(xi, 0), WW - 1);
    // y_img = trunc(-xp/0.2) + 352, clip [0, H-1]
    int yi = (int)__fdiv_rn(-xp, 0.2f) + 352;
    yi = min(max(yi, 0), HH - 1);

    int xf = WW - 1 - xi;
    int yf = HH - 1 - yi;
    int cell = (zbin * WW + xf) * HH + yf;

    // Last point index wins (XLA scatter applies updates in order)
    atomicMax(&g_winner[b * DWH + cell], n);
}

// One thread owns 4 consecutive cells; winner int4 loaded ONCE into registers,
// then reused across all 64 channels (kills the 64x winner re-read from L2).
__global__ void __launch_bounds__(256) write_bev_kernel(
        const float* __restrict__ feat, float* __restrict__ out) {
    const int b = blockIdx.y;
    const int base = blockIdx.x * TILE;          // cell base for this block
    const int t = threadIdx.x;
    if (t >= TILE / 4) return;                   // 250 active threads

    const int cell0 = base + t * 4;
    const int4 w = *reinterpret_cast<const int4*>(&g_winner[b * DWH + cell0]);

    const float* fb = feat + (long long)b * CC * NN;
    float* ob = out + ((long long)b * CC) * DWH + cell0;

    #pragma unroll 4
    for (int c = 0; c < CC; c++) {
        const float* plane = fb + (long long)c * NN;
        float4 r;
        r.x = (w.x >= 0) ? __ldg(plane + w.x) : 0.0f;
        r.y = (w.y >= 0) ? __ldg(plane + w.y) : 0.0f;
        r.z = (w.z >= 0) ? __ldg(plane + w.z) : 0.0f;
        r.w = (w.w >= 0) ? __ldg(plane + w.w) : 0.0f;
        *reinterpret_cast<float4*>(ob + (long long)c * DWH) = r;
    }
}

extern "C" void kernel_launch(void* const* d_in, const int* in_sizes, int n_in,
                              void* d_out, int out_size) {
    const float* range_res = (const float*)d_in[0];   // (B, C, RH, RW)
    const float* xyz       = (const float*)d_in[1];   // (B, 3, RH, RW)
    float* out = (float*)d_out;                       // (B, C, D, W, H)

    // 1) winner map := -1
    {
        int n4 = (BB * DWH) / 4;
        init_winner_kernel<<<(n4 + 255) / 256, 256>>>();
    }
    // 2) resolve winners (last index wins)
    {
        int npts = BB * NN;
        scatter_winner_kernel<<<(npts + 255) / 256, 256>>>(xyz);
    }
    // 3) register-cached-winner gather/write of the full output
    {
        dim3 grid(DWH / TILE, BB);   // (704, 2)
        write_bev_kernel<<<grid, 256>>>(range_res, out);
    }
}